// round 14
// baseline (speedup 1.0000x reference)
#include <cuda_runtime.h>
#include <math.h>

#define TT 256
#define DD 64
#define SS 64
#define VV 32
#define BPB 14           // batches per block -> grid 293 = single wave at 2 CTAs/SM
#define LCAP 3584        // packed list capacity (map front, step back)

typedef unsigned long long u64;

// ---------------- shared layout (floats) ----------------
#define OFF_W1M   0        // 4096 quad-interleaved
#define OFF_W1S   4096     // 4096
#define OFF_B1M   8192     // 64
#define OFF_W2M   8256     // 64
#define OFF_B1S   8320     // 64
#define OFF_W2S   8384     // 64
#define OFF_LIST  8448     // 3584 ints (map front / step back)
#define OFF_GAIN  12032    // 3584 floats (index-aligned with LIST)
#define OFF_X     15616    // 8 warps * 2 buffers * 8 tok * 64 = 8192
#define OFF_WALK  23808    // 14*64
#define OFF_NW    24704    // 14*64
#define OFF_WSUM  25600    // 14*64
#define OFF_ACCV  26496    // 14*32
#define OFF_CNT   26944    // 2 ints
#define SMEM_FLOATS 26948  // 107792 bytes; 2 CTAs = 215584 <= 228KB

// tail overlay on LIST+GAIN region (7168 floats), stride-16 batch rows
#define HT_WS 0            // 96*16  = 1536
#define HT_GS 1536         // 128*16 = 2048
#define HT_H  3584         // 128*16 = 2048

// tanh-form GELU with single-instruction MUFU.TANH.
__device__ __forceinline__ float gelu_fast(float x) {
    float x2 = x * x;
    float inner = x * fmaf(0.044715f, x2, 1.0f);
    float arg = 0.79788456080286535588f * inner;
    float th;
    asm("tanh.approx.f32 %0, %1;" : "=f"(th) : "f"(arg));
    return 0.5f * x * (1.0f + th);
}

__device__ __forceinline__ u64 ffma2(u64 a, u64 b, u64 c) {
    u64 d;
    asm("fma.rn.f32x2 %0, %1, %2, %3;" : "=l"(d) : "l"(a), "l"(b), "l"(c));
    return d;
}
__device__ __forceinline__ u64 packdup(float x) {
    u64 d;
    asm("mov.b64 %0, {%1, %1};" : "=l"(d) : "f"(x));
    return d;
}

// warp-cooperative gate MLP, 8 tokens/pass, double-buffered staging:
// one syncwarp per pass; LDG(next) hidden under FMA, STS(next) hidden under epilogue.
// Quad weight layout: Wq[kq*256 + f*4 + j] = W[4kq+j][f]
// item: tok[0:8) | bi[8:12) | src[12:18) | tgt[18:24)
__device__ __forceinline__ void process_events8(
    const int* __restrict__ list, int n, float b2,
    float* __restrict__ gout,
    const float* __restrict__ sWq, const float* __restrict__ sb1,
    const float* __restrict__ sw2,
    const float* __restrict__ evidence, int b0,
    float* __restrict__ sXw, int lane)
{
    const int wid = threadIdx.x >> 5;
    const int sel = lane >> 4;           // 0: even token of pair, 1: odd
    const int sub = lane & 15;           // 16B chunk within row

    int items[8];
    bool valid[8];
    float4 vreg[4];

    int base = wid * 8;
    if (base >= n) return;

    // prologue: gather pass0 and stage into buffer 0
#pragma unroll
    for (int i = 0; i < 8; i++) {
        int idx = base + i;
        valid[i] = (idx < n);
        items[i] = list[valid[i] ? idx : (n - 1)];
    }
#pragma unroll
    for (int i = 0; i < 8; i += 2) {
        int it = items[i + sel];
        int tok = it & 255;
        int bb  = (it >> 8) & 15;
        vreg[i >> 1] = *((const float4*)(evidence + ((size_t)(b0 + bb) * TT + tok) * DD) + sub);
    }
#pragma unroll
    for (int i = 0; i < 8; i += 2)
        *(float4*)(sXw + (i + sel) * DD + sub * 4) = vreg[i >> 1];

    int cur = 0;
    for (; base < n; base += 64) {
        __syncwarp();   // buf_cur stores visible to all lanes

        const float* bc = sXw + cur * 512;
        float*       bn = sXw + (cur ^ 1) * 512;

        bool cur_valid[8];
#pragma unroll
        for (int i = 0; i < 8; i++) cur_valid[i] = valid[i];

        // issue gather for next pass (LDG latency covered by FMA loop)
        const int next = base + 64;
        const bool have_next = (next < n);
        if (have_next) {
#pragma unroll
            for (int i = 0; i < 8; i++) {
                int idx = next + i;
                valid[i] = (idx < n);
                items[i] = list[valid[i] ? idx : (n - 1)];
            }
#pragma unroll
            for (int i = 0; i < 8; i += 2) {
                int it = items[i + sel];
                int tok = it & 255;
                int bb  = (it >> 8) & 15;
                vreg[i >> 1] = *((const float4*)(evidence + ((size_t)(b0 + bb) * TT + tok) * DD) + sub);
            }
        }

        u64 acc0[8], acc1[8];
#pragma unroll
        for (int i = 0; i < 8; i++) { acc0[i] = 0ull; acc1[i] = 0ull; }

#pragma unroll
        for (int kq = 0; kq < DD / 4; kq++) {
            ulonglong2 wa = *(const ulonglong2*)(sWq + kq * 256 + 4 * lane);        // feat l, k-quad
            ulonglong2 wb = *(const ulonglong2*)(sWq + kq * 256 + 128 + 4 * lane);  // feat l+32
#pragma unroll
            for (int i = 0; i < 8; i++) {
                ulonglong2 xq = *(const ulonglong2*)(bc + i * DD + 4 * kq);  // broadcast LDS.128
                acc0[i] = ffma2(xq.x, wa.x, acc0[i]);
                acc0[i] = ffma2(xq.y, wa.y, acc0[i]);
                acc1[i] = ffma2(xq.x, wb.x, acc1[i]);
                acc1[i] = ffma2(xq.y, wb.y, acc1[i]);
            }
        }

        // stage next pass into the other buffer (overlaps with epilogue below)
        if (have_next) {
#pragma unroll
            for (int i = 0; i < 8; i += 2)
                *(float4*)(bn + (i + sel) * DD + sub * 4) = vreg[i >> 1];
        }

        float b1a = sb1[lane], b1b = sb1[lane + 32];
        float w2a = sw2[lane], w2b = sw2[lane + 32];
#pragma unroll
        for (int i = 0; i < 8; i++) {
            float lo, hi;
            asm("mov.b64 {%0,%1}, %2;" : "=f"(lo), "=f"(hi) : "l"(acc0[i]));
            float h0 = lo + hi + b1a;
            asm("mov.b64 {%0,%1}, %2;" : "=f"(lo), "=f"(hi) : "l"(acc1[i]));
            float h1 = lo + hi + b1b;
            float p = gelu_fast(h0) * w2a + gelu_fast(h1) * w2b;
#pragma unroll
            for (int off = 16; off; off >>= 1)
                p += __shfl_xor_sync(0xffffffffu, p, off);
            if (lane == 0 && cur_valid[i]) {
                gout[base + i] = 1.0f / (1.0f + __expf(-(p + b2)));
            }
        }

        cur ^= 1;
    }
}

__global__ __launch_bounds__(256, 2)
void cpm_fused_kernel(
    const float* __restrict__ evidence,
    const int* __restrict__ marker,
    const int* __restrict__ src_idx,
    const int* __restrict__ src_valid,
    const int* __restrict__ tsym_idx,
    const int* __restrict__ tsym_valid,
    const int* __restrict__ tval_idx,
    const int* __restrict__ tval_valid,
    const int* __restrict__ query_idx,
    const int* __restrict__ query_valid,
    const float* __restrict__ symbol_emb,
    const float* __restrict__ value_emb,
    const float* __restrict__ mg_W1, const float* __restrict__ mg_b1,
    const float* __restrict__ mg_W2, const float* __restrict__ mg_b2,
    const float* __restrict__ sg_W1, const float* __restrict__ sg_b1,
    const float* __restrict__ sg_W2, const float* __restrict__ sg_b2,
    const float* __restrict__ sf_W1, const float* __restrict__ sf_b1,
    const float* __restrict__ sf_W2, const float* __restrict__ sf_b2,
    const float* __restrict__ oh_W1, const float* __restrict__ oh_b1,
    const float* __restrict__ oh_W2, const float* __restrict__ oh_b2,
    float* __restrict__ out, int B)
{
    extern __shared__ float sm[];
    float* sW1m  = sm + OFF_W1M;
    float* sW1s  = sm + OFF_W1S;
    float* sb1m  = sm + OFF_B1M;
    float* sw2m  = sm + OFF_W2M;
    float* sb1s  = sm + OFF_B1S;
    float* sw2s  = sm + OFF_W2S;
    int*   sList = (int*)(sm + OFF_LIST);
    float* sGain = sm + OFF_GAIN;
    float* sX    = sm + OFF_X;
    float* sWalk = sm + OFF_WALK;
    float* sNw   = sm + OFF_NW;
    float* sWsum = sm + OFF_WSUM;
    float* sAccv = sm + OFF_ACCV;
    int*   sCnt  = (int*)(sm + OFF_CNT);

    const int tid  = threadIdx.x;
    const int lane = tid & 31;
    const int wid  = tid >> 5;
    const int b0   = blockIdx.x * BPB;

    if (tid < 2) sCnt[tid] = 0;

    // prefetch gate weights into registers (overlap with list build)
    float wrm[16], wrs[16];
#pragma unroll
    for (int i = 0; i < 16; i++) {
        wrm[i] = mg_W1[tid + 256 * i];
        wrs[i] = sg_W1[tid + 256 * i];
    }
    __syncthreads();

    // build packed compact event lists (map from front, step from back)
#pragma unroll
    for (int bi = 0; bi < BPB; bi++) {
        const int b = b0 + bi;
        if (b >= B) break;
        const int gt = b * TT + tid;
        int m  = marker[gt];
        int sv = src_valid[gt];
        if (sv != 0) {
            int si = min(max(src_idx[gt], 0), SS - 1);
            if (m == 1 || m == 2) {
                if (tval_valid[gt] != 0) {
                    int tv = min(max(tval_idx[gt], 0), VV - 1);
                    int p = atomicAdd(&sCnt[0], 1);
                    sList[p] = tid | (bi << 8) | (si << 12) | (tv << 18);
                }
            } else if (m == 3) {
                if (tsym_valid[gt] != 0) {
                    int ts = min(max(tsym_idx[gt], 0), SS - 1);
                    int p = atomicAdd(&sCnt[1], 1);
                    sList[LCAP - 1 - p] = tid | (bi << 8) | (si << 12) | (ts << 18);
                }
            }
        }
    }

    // store prefetched weights, k-quad interleaved
#pragma unroll
    for (int i = 0; i < 16; i++) {
        int idx = tid + 256 * i;
        int k = idx >> 6, f = idx & 63;
        int dst = (k >> 2) * 256 + (f << 2) + (k & 3);
        sW1m[dst] = wrm[i];
        sW1s[dst] = wrs[i];
    }
    if (tid < DD) {
        sb1m[tid] = mg_b1[tid]; sw2m[tid] = mg_W2[tid];
        sb1s[tid] = sg_b1[tid]; sw2s[tid] = sg_W2[tid];
    }
    __syncthreads();

    const int nmap  = sCnt[0];
    const int nstep = sCnt[1];
    const int*   lstep = sList + LCAP - nstep;
    float*       gstep = sGain + LCAP - nstep;
    float* sXw = sX + wid * 1024;        // two 512-float buffers per warp

    process_events8(sList, nmap, mg_b2[0], sGain, sW1m, sb1m, sw2m,
                    evidence, b0, sXw, lane);
    process_events8(lstep, nstep, sg_b2[0], gstep, sW1s, sb1s, sw2s,
                    evidence, b0, sXw, lane);
    __syncthreads();

    // ---- sparse walk: warps cover 14 batches in two rounds ----
#pragma unroll
    for (int ph = 0; ph < 2; ph++) {
        const int bi = wid + ph * 8;
        if (bi < BPB) {
            const int b = b0 + bi;
            float* walk = sWalk + bi * SS;
            float* nw   = sNw   + bi * SS;
            float* wsum = sWsum + bi * SS;
            float* accv = sAccv + bi * VV;
            if (b < B) {
                int q = min(max(query_idx[b], 0), SS - 1);
                float qv = (float)query_valid[b];
#pragma unroll
                for (int i = lane; i < SS; i += 32) {
                    float w = (i == q) ? qv : 0.f;
                    walk[i] = w; wsum[i] = w;
                }
                if (lane < VV) accv[lane] = 0.f;
                __syncwarp();

                for (int it = 0; it < 3; it++) {
#pragma unroll
                    for (int i = lane; i < SS; i += 32) nw[i] = 0.f;
                    __syncwarp();
                    for (int e = lane; e < nstep; e += 32) {
                        int item = lstep[e];
                        if (((item >> 8) & 15) == bi) {
                            int src = (item >> 12) & 63;
                            int tgt = (item >> 18) & 63;
                            atomicAdd(&nw[tgt], gstep[e] * walk[src]);
                        }
                    }
                    __syncwarp();
#pragma unroll
                    for (int i = lane; i < SS; i += 32) {
                        float w = nw[i];
                        walk[i] = w; wsum[i] += w;
                    }
                    __syncwarp();
                }
                for (int e = lane; e < nmap; e += 32) {
                    int item = sList[e];
                    if (((item >> 8) & 15) == bi) {
                        int src = (item >> 12) & 63;
                        int tv  = (item >> 18) & 63;
                        atomicAdd(&accv[tv], sGain[e] * wsum[src]);
                    }
                }
            } else {
                if (lane < VV) accv[lane] = 0.f;
#pragma unroll
                for (int i = lane; i < SS; i += 32) wsum[i] = 0.f;
            }
        }
    }
    __syncthreads();

    // ==== fused heads: overlay transposed states on dead list/gain region ====
    float* wsT = sm + OFF_LIST + HT_WS;   // [96][16]
    float* gsT = sm + OFF_LIST + HT_GS;   // [128][16]
    float* hT  = sm + OFF_LIST + HT_H;    // [128][16]

    for (int idx = tid; idx < 96 * 16; idx += 256) {
        int j = idx >> 4, bi = idx & 15;
        float v = 0.f;
        if (bi < BPB)
            v = (j < 64) ? sWsum[bi * SS + j] : sAccv[bi * VV + (j - 64)];
        wsT[j * 16 + bi] = v;
    }
    __syncthreads();

    const int col  = tid & 127;
    const int half = tid >> 7;          // 8 batch-slots per half
    const int boff = half * 8;

    // ---- phase A: gs_T[col][bi] ----
    {
        u64 acc[4] = {0ull, 0ull, 0ull, 0ull};
        if (col < DD) {
#pragma unroll 8
            for (int s = 0; s < SS; s++) {
                u64 wd = packdup(__ldg(symbol_emb + s * DD + col));
                const float* row = wsT + s * 16 + boff;
#pragma unroll
                for (int p = 0; p < 4; p++)
                    acc[p] = ffma2(*(const u64*)(row + 2 * p), wd, acc[p]);
            }
        } else {
            const int d = col - DD;
#pragma unroll 8
            for (int v = 0; v < VV; v++) {
                u64 wd = packdup(__ldg(value_emb + v * DD + d));
                const float* row = wsT + (64 + v) * 16 + boff;
#pragma unroll
                for (int p = 0; p < 4; p++)
                    acc[p] = ffma2(*(const u64*)(row + 2 * p), wd, acc[p]);
            }
        }
        float* grow = gsT + col * 16 + boff;
#pragma unroll
        for (int p = 0; p < 4; p++) *(u64*)(grow + 2 * p) = acc[p];
    }
    __syncthreads();

    // ---- phase B: h_T[col][bi] = gelu(bias + gs @ W1) ----
    {
        u64 acc[4] = {0ull, 0ull, 0ull, 0ull};
        const float* W1 = (col < DD) ? (oh_W1 + col) : (sf_W1 + col - DD);
#pragma unroll 8
        for (int k = 0; k < 2 * DD; k++) {
            u64 wd = packdup(__ldg(W1 + k * DD));
            const float* row = gsT + k * 16 + boff;
#pragma unroll
            for (int p = 0; p < 4; p++)
                acc[p] = ffma2(*(const u64*)(row + 2 * p), wd, acc[p]);
        }
        float bias = (col < DD) ? oh_b1[col] : sf_b1[col - DD];
        float* hrow = hT + col * 16 + boff;
#pragma unroll
        for (int p = 0; p < 4; p++) {
            float lo, hi;
            asm("mov.b64 {%0,%1}, %2;" : "=f"(lo), "=f"(hi) : "l"(acc[p]));
            hrow[2 * p]     = gelu_fast(lo + bias);
            hrow[2 * p + 1] = gelu_fast(hi + bias);
        }
    }
    __syncthreads();

    // ---- phase C: outputs (col < 96 per half) ----
    if (col < 96) {
        const int j = col;
        u64 acc[4] = {0ull, 0ull, 0ull, 0ull};
        if (j < VV) {
#pragma unroll 8
            for (int k = 0; k < DD; k++) {
                u64 wd = packdup(__ldg(oh_W2 + k * VV + j));
                const float* row = hT + k * 16 + boff;
#pragma unroll
                for (int p = 0; p < 4; p++)
                    acc[p] = ffma2(*(const u64*)(row + 2 * p), wd, acc[p]);
            }
            float bias = oh_b2[j];
#pragma unroll
            for (int p = 0; p < 4; p++) {
                float lo, hi;
                asm("mov.b64 {%0,%1}, %2;" : "=f"(lo), "=f"(hi) : "l"(acc[p]));
                int bi0 = boff + 2 * p;
                int b = b0 + bi0;
                if (bi0 < BPB && b < B)         out[(size_t)b * VV + j] = lo + bias;
                if (bi0 + 1 < BPB && b + 1 < B) out[(size_t)(b + 1) * VV + j] = hi + bias;
            }
        } else {
            const int d = j - VV;
#pragma unroll 8
            for (int k = 0; k < DD; k++) {
                u64 wd = packdup(__ldg(sf_W2 + k * DD + d));
                const float* row = hT + (64 + k) * 16 + boff;
#pragma unroll
                for (int p = 0; p < 4; p++)
                    acc[p] = ffma2(*(const u64*)(row + 2 * p), wd, acc[p]);
            }
            float bias = sf_b2[d];
            float* fb = out + (size_t)B * VV;
#pragma unroll
            for (int p = 0; p < 4; p++) {
                float lo, hi;
                asm("mov.b64 {%0,%1}, %2;" : "=f"(lo), "=f"(hi) : "l"(acc[p]));
                int bi0 = boff + 2 * p;
                int b = b0 + bi0;
                if (bi0 < BPB && b < B)         fb[(size_t)b * DD + d] = lo + bias;
                if (bi0 + 1 < BPB && b + 1 < B) fb[(size_t)(b + 1) * DD + d] = hi + bias;
            }
        }
    }
}

extern "C" void kernel_launch(void* const* d_in, const int* in_sizes, int n_in,
                              void* d_out, int out_size)
{
    const float* evidence    = (const float*)d_in[0];
    const int*   marker      = (const int*)d_in[1];
    const int*   src_idx     = (const int*)d_in[2];
    const int*   src_valid   = (const int*)d_in[3];
    const int*   tsym_idx    = (const int*)d_in[4];
    const int*   tsym_valid  = (const int*)d_in[5];
    const int*   tval_idx    = (const int*)d_in[6];
    const int*   tval_valid  = (const int*)d_in[7];
    const int*   query_idx   = (const int*)d_in[8];
    const int*   query_valid = (const int*)d_in[9];
    const float* symbol_emb  = (const float*)d_in[10];
    const float* value_emb   = (const float*)d_in[11];
    const float* mg_W1 = (const float*)d_in[12];
    const float* mg_b1 = (const float*)d_in[13];
    const float* mg_W2 = (const float*)d_in[14];
    const float* mg_b2 = (const float*)d_in[15];
    const float* sg_W1 = (const float*)d_in[16];
    const float* sg_b1 = (const float*)d_in[17];
    const float* sg_W2 = (const float*)d_in[18];
    const float* sg_b2 = (const float*)d_in[19];
    const float* sf_W1 = (const float*)d_in[20];
    const float* sf_b1 = (const float*)d_in[21];
    const float* sf_W2 = (const float*)d_in[22];
    const float* sf_b2 = (const float*)d_in[23];
    const float* oh_W1 = (const float*)d_in[24];
    const float* oh_b1 = (const float*)d_in[25];
    const float* oh_W2 = (const float*)d_in[26];
    const float* oh_b2 = (const float*)d_in[27];

    const int B = in_sizes[8];

    const int smem = SMEM_FLOATS * (int)sizeof(float);
    cudaFuncSetAttribute(cpm_fused_kernel, cudaFuncAttributeMaxDynamicSharedMemorySize, smem);

    const int grid = (B + BPB - 1) / BPB;
    cpm_fused_kernel<<<grid, 256, smem>>>(
        evidence, marker, src_idx, src_valid, tsym_idx, tsym_valid,
        tval_idx, tval_valid, query_idx, query_valid,
        symbol_emb, value_emb,
        mg_W1, mg_b1, mg_W2, mg_b2,
        sg_W1, sg_b1, sg_W2, sg_b2,
        sf_W1, sf_b1, sf_W2, sf_b2,
        oh_W1, oh_b1, oh_W2, oh_b2,
        (float*)d_out, B);
}

// round 15
// speedup vs baseline: 1.1306x; 1.1306x over previous
#include <cuda_runtime.h>
#include <math.h>

#define TT 256
#define DD 64
#define SS 64
#define VV 32
#define BPB 14           // batches per block -> grid 293 = single wave at 2 CTAs/SM
#define LCAP 3584        // packed list capacity (map front, step back)

typedef unsigned long long u64;

// ---------------- shared layout (floats) ----------------
#define OFF_W1M   0        // 4096 quad-interleaved
#define OFF_W1S   4096     // 4096
#define OFF_B1M   8192     // 64
#define OFF_W2M   8256     // 64
#define OFF_B1S   8320     // 64
#define OFF_W2S   8384     // 64
#define OFF_LIST  8448     // 3584 ints (map front / step back)
#define OFF_GAIN  12032    // 3584 floats (index-aligned with LIST)
#define OFF_X     15616    // 8 warps * 8 tok * 64 = 4096
#define OFF_WALK  19712    // 14*64
#define OFF_NW    20608    // 14*64
#define OFF_WSUM  21504    // 14*64
#define OFF_ACCV  22400    // 14*32
#define OFF_CNT   22848    // 2 ints
#define SMEM_FLOATS 22852  // 91408 bytes

// tail overlay on LIST+GAIN region (7168 floats), stride-16 batch rows
#define HT_WS 0            // 96*16  = 1536
#define HT_GS 1536         // 128*16 = 2048
#define HT_H  3584         // 128*16 = 2048

// tanh-form GELU with single-instruction MUFU.TANH.
__device__ __forceinline__ float gelu_fast(float x) {
    float x2 = x * x;
    float inner = x * fmaf(0.044715f, x2, 1.0f);
    float arg = 0.79788456080286535588f * inner;
    float th;
    asm("tanh.approx.f32 %0, %1;" : "=f"(th) : "f"(arg));
    return 0.5f * x * (1.0f + th);
}

__device__ __forceinline__ u64 ffma2(u64 a, u64 b, u64 c) {
    u64 d;
    asm("fma.rn.f32x2 %0, %1, %2, %3;" : "=l"(d) : "l"(a), "l"(b), "l"(c));
    return d;
}
__device__ __forceinline__ u64 packdup(float x) {
    u64 d;
    asm("mov.b64 %0, {%1, %1};" : "=l"(d) : "f"(x));
    return d;
}

// warp-cooperative gate MLP, 8 tokens/pass, gather pipelined one pass ahead.
// Quad weight layout: Wq[kq*256 + f*4 + j] = W[4kq+j][f]
// item: tok[0:8) | bi[8:12) | src[12:18) | tgt[18:24)
// Epilogue: multi-token butterfly reduction — 8 independent 32-lane sums in 9 shfls.
__device__ __forceinline__ void process_events8(
    const int* __restrict__ list, int n, float b2,
    float* __restrict__ gout,
    const float* __restrict__ sWq, const float* __restrict__ sb1,
    const float* __restrict__ sw2,
    const float* __restrict__ evidence, int b0,
    float* __restrict__ sXw, int lane)
{
    const int wid = threadIdx.x >> 5;
    const int sel = lane >> 4;           // 0: even token of pair, 1: odd
    const int sub = lane & 15;           // 16B chunk within row
    const int sel16 = (lane >> 4) & 1;
    const int sel8  = (lane >> 3) & 1;
    const int sel4  = (lane >> 2) & 1;
    const int tok_id = lane >> 2;        // reduction output token for this lane group
    const bool writer = (lane & 3) == 0;

    int items[8];
    float4 vreg[4];

    int base = wid * 8;
    if (base < n) {
#pragma unroll
        for (int i = 0; i < 8; i++) {
            int idx = base + i;
            items[i] = list[(idx < n) ? idx : (n - 1)];
        }
#pragma unroll
        for (int i = 0; i < 8; i += 2) {
            int it = items[i + sel];
            int tok = it & 255;
            int bb  = (it >> 8) & 15;
            vreg[i >> 1] = *((const float4*)(evidence + ((size_t)(b0 + bb) * TT + tok) * DD) + sub);
        }
    }

    for (; base < n; base += 64) {
        // store staged gather for this pass
#pragma unroll
        for (int i = 0; i < 8; i += 2)
            *(float4*)(sXw + (i + sel) * DD + sub * 4) = vreg[i >> 1];
        __syncwarp();

        // issue gather for next pass (latency covered by FMA loop below)
        int next = base + 64;
        if (next < n) {
#pragma unroll
            for (int i = 0; i < 8; i++) {
                int idx = next + i;
                items[i] = list[(idx < n) ? idx : (n - 1)];
            }
#pragma unroll
            for (int i = 0; i < 8; i += 2) {
                int it = items[i + sel];
                int tok = it & 255;
                int bb  = (it >> 8) & 15;
                vreg[i >> 1] = *((const float4*)(evidence + ((size_t)(b0 + bb) * TT + tok) * DD) + sub);
            }
        }

        u64 acc0[8], acc1[8];
#pragma unroll
        for (int i = 0; i < 8; i++) { acc0[i] = 0ull; acc1[i] = 0ull; }

#pragma unroll
        for (int kq = 0; kq < DD / 4; kq++) {
            ulonglong2 wa = *(const ulonglong2*)(sWq + kq * 256 + 4 * lane);        // feat l, k-quad
            ulonglong2 wb = *(const ulonglong2*)(sWq + kq * 256 + 128 + 4 * lane);  // feat l+32
#pragma unroll
            for (int i = 0; i < 8; i++) {
                ulonglong2 xq = *(const ulonglong2*)(sXw + i * DD + 4 * kq);  // broadcast LDS.128
                acc0[i] = ffma2(xq.x, wa.x, acc0[i]);
                acc0[i] = ffma2(xq.y, wa.y, acc0[i]);
                acc1[i] = ffma2(xq.x, wb.x, acc1[i]);
                acc1[i] = ffma2(xq.y, wb.y, acc1[i]);
            }
        }

        float b1a = sb1[lane], b1b = sb1[lane + 32];
        float w2a = sw2[lane], w2b = sw2[lane + 32];
        float p[8];
#pragma unroll
        for (int i = 0; i < 8; i++) {
            float lo, hi;
            asm("mov.b64 {%0,%1}, %2;" : "=f"(lo), "=f"(hi) : "l"(acc0[i]));
            float h0 = lo + hi + b1a;
            asm("mov.b64 {%0,%1}, %2;" : "=f"(lo), "=f"(hi) : "l"(acc1[i]));
            float h1 = lo + hi + b1b;
            p[i] = gelu_fast(h0) * w2a + gelu_fast(h1) * w2b;
        }

        // multi-token fold: xor16 (8->4 tokens/lane), xor8 (4->2), xor4 (2->1),
        // then xor2 + xor1 finish the 4-lane partial sums. 9 shfls total.
        float q[4];
#pragma unroll
        for (int j = 0; j < 4; j++) {
            float snd = sel16 ? p[j] : p[j + 4];
            float kp  = sel16 ? p[j + 4] : p[j];
            q[j] = kp + __shfl_xor_sync(0xffffffffu, snd, 16);
        }
        float r[2];
#pragma unroll
        for (int j = 0; j < 2; j++) {
            float snd = sel8 ? q[j] : q[j + 2];
            float kp  = sel8 ? q[j + 2] : q[j];
            r[j] = kp + __shfl_xor_sync(0xffffffffu, snd, 8);
        }
        float s;
        {
            float snd = sel4 ? r[0] : r[1];
            float kp  = sel4 ? r[1] : r[0];
            s = kp + __shfl_xor_sync(0xffffffffu, snd, 4);
        }
        s += __shfl_xor_sync(0xffffffffu, s, 2);
        s += __shfl_xor_sync(0xffffffffu, s, 1);

        if (writer) {
            int idx = base + tok_id;
            if (idx < n)
                gout[idx] = 1.0f / (1.0f + __expf(-(s + b2)));
        }
        __syncwarp();
    }
}

__global__ __launch_bounds__(256, 2)
void cpm_fused_kernel(
    const float* __restrict__ evidence,
    const int* __restrict__ marker,
    const int* __restrict__ src_idx,
    const int* __restrict__ src_valid,
    const int* __restrict__ tsym_idx,
    const int* __restrict__ tsym_valid,
    const int* __restrict__ tval_idx,
    const int* __restrict__ tval_valid,
    const int* __restrict__ query_idx,
    const int* __restrict__ query_valid,
    const float* __restrict__ symbol_emb,
    const float* __restrict__ value_emb,
    const float* __restrict__ mg_W1, const float* __restrict__ mg_b1,
    const float* __restrict__ mg_W2, const float* __restrict__ mg_b2,
    const float* __restrict__ sg_W1, const float* __restrict__ sg_b1,
    const float* __restrict__ sg_W2, const float* __restrict__ sg_b2,
    const float* __restrict__ sf_W1, const float* __restrict__ sf_b1,
    const float* __restrict__ sf_W2, const float* __restrict__ sf_b2,
    const float* __restrict__ oh_W1, const float* __restrict__ oh_b1,
    const float* __restrict__ oh_W2, const float* __restrict__ oh_b2,
    float* __restrict__ out, int B)
{
    extern __shared__ float sm[];
    float* sW1m  = sm + OFF_W1M;
    float* sW1s  = sm + OFF_W1S;
    float* sb1m  = sm + OFF_B1M;
    float* sw2m  = sm + OFF_W2M;
    float* sb1s  = sm + OFF_B1S;
    float* sw2s  = sm + OFF_W2S;
    int*   sList = (int*)(sm + OFF_LIST);
    float* sGain = sm + OFF_GAIN;
    float* sX    = sm + OFF_X;
    float* sWalk = sm + OFF_WALK;
    float* sNw   = sm + OFF_NW;
    float* sWsum = sm + OFF_WSUM;
    float* sAccv = sm + OFF_ACCV;
    int*   sCnt  = (int*)(sm + OFF_CNT);

    const int tid  = threadIdx.x;
    const int lane = tid & 31;
    const int wid  = tid >> 5;
    const int b0   = blockIdx.x * BPB;

    if (tid < 2) sCnt[tid] = 0;

    // prefetch gate weights into registers (overlap with list build)
    float wrm[16], wrs[16];
#pragma unroll
    for (int i = 0; i < 16; i++) {
        wrm[i] = mg_W1[tid + 256 * i];
        wrs[i] = sg_W1[tid + 256 * i];
    }
    __syncthreads();

    // build packed compact event lists (map from front, step from back)
#pragma unroll
    for (int bi = 0; bi < BPB; bi++) {
        const int b = b0 + bi;
        if (b >= B) break;
        const int gt = b * TT + tid;
        int m  = marker[gt];
        int sv = src_valid[gt];
        if (sv != 0) {
            int si = min(max(src_idx[gt], 0), SS - 1);
            if (m == 1 || m == 2) {
                if (tval_valid[gt] != 0) {
                    int tv = min(max(tval_idx[gt], 0), VV - 1);
                    int p = atomicAdd(&sCnt[0], 1);
                    sList[p] = tid | (bi << 8) | (si << 12) | (tv << 18);
                }
            } else if (m == 3) {
                if (tsym_valid[gt] != 0) {
                    int ts = min(max(tsym_idx[gt], 0), SS - 1);
                    int p = atomicAdd(&sCnt[1], 1);
                    sList[LCAP - 1 - p] = tid | (bi << 8) | (si << 12) | (ts << 18);
                }
            }
        }
    }

    // store prefetched weights, k-quad interleaved
#pragma unroll
    for (int i = 0; i < 16; i++) {
        int idx = tid + 256 * i;
        int k = idx >> 6, f = idx & 63;
        int dst = (k >> 2) * 256 + (f << 2) + (k & 3);
        sW1m[dst] = wrm[i];
        sW1s[dst] = wrs[i];
    }
    if (tid < DD) {
        sb1m[tid] = mg_b1[tid]; sw2m[tid] = mg_W2[tid];
        sb1s[tid] = sg_b1[tid]; sw2s[tid] = sg_W2[tid];
    }
    __syncthreads();

    const int nmap  = sCnt[0];
    const int nstep = sCnt[1];
    const int*   lstep = sList + LCAP - nstep;
    float*       gstep = sGain + LCAP - nstep;
    float* sXw = sX + wid * 8 * DD;

    process_events8(sList, nmap, mg_b2[0], sGain, sW1m, sb1m, sw2m,
                    evidence, b0, sXw, lane);
    process_events8(lstep, nstep, sg_b2[0], gstep, sW1s, sb1s, sw2s,
                    evidence, b0, sXw, lane);
    __syncthreads();

    // ---- sparse walk: warps cover 14 batches in two rounds ----
#pragma unroll
    for (int ph = 0; ph < 2; ph++) {
        const int bi = wid + ph * 8;
        if (bi < BPB) {
            const int b = b0 + bi;
            float* walk = sWalk + bi * SS;
            float* nw   = sNw   + bi * SS;
            float* wsum = sWsum + bi * SS;
            float* accv = sAccv + bi * VV;
            if (b < B) {
                int q = min(max(query_idx[b], 0), SS - 1);
                float qv = (float)query_valid[b];
#pragma unroll
                for (int i = lane; i < SS; i += 32) {
                    float w = (i == q) ? qv : 0.f;
                    walk[i] = w; wsum[i] = w;
                }
                if (lane < VV) accv[lane] = 0.f;
                __syncwarp();

                for (int it = 0; it < 3; it++) {
#pragma unroll
                    for (int i = lane; i < SS; i += 32) nw[i] = 0.f;
                    __syncwarp();
                    for (int e = lane; e < nstep; e += 32) {
                        int item = lstep[e];
                        if (((item >> 8) & 15) == bi) {
                            int src = (item >> 12) & 63;
                            int tgt = (item >> 18) & 63;
                            atomicAdd(&nw[tgt], gstep[e] * walk[src]);
                        }
                    }
                    __syncwarp();
#pragma unroll
                    for (int i = lane; i < SS; i += 32) {
                        float w = nw[i];
                        walk[i] = w; wsum[i] += w;
                    }
                    __syncwarp();
                }
                for (int e = lane; e < nmap; e += 32) {
                    int item = sList[e];
                    if (((item >> 8) & 15) == bi) {
                        int src = (item >> 12) & 63;
                        int tv  = (item >> 18) & 63;
                        atomicAdd(&accv[tv], sGain[e] * wsum[src]);
                    }
                }
            } else {
                if (lane < VV) accv[lane] = 0.f;
#pragma unroll
                for (int i = lane; i < SS; i += 32) wsum[i] = 0.f;
            }
        }
    }
    __syncthreads();

    // ==== fused heads: overlay transposed states on dead list/gain region ====
    float* wsT = sm + OFF_LIST + HT_WS;   // [96][16]
    float* gsT = sm + OFF_LIST + HT_GS;   // [128][16]
    float* hT  = sm + OFF_LIST + HT_H;    // [128][16]

    for (int idx = tid; idx < 96 * 16; idx += 256) {
        int j = idx >> 4, bi = idx & 15;
        float v = 0.f;
        if (bi < BPB)
            v = (j < 64) ? sWsum[bi * SS + j] : sAccv[bi * VV + (j - 64)];
        wsT[j * 16 + bi] = v;
    }
    __syncthreads();

    const int col  = tid & 127;
    const int half = tid >> 7;          // 8 batch-slots per half
    const int boff = half * 8;

    // ---- phase A: gs_T[col][bi] ----
    {
        u64 acc[4] = {0ull, 0ull, 0ull, 0ull};
        if (col < DD) {
#pragma unroll 8
            for (int s = 0; s < SS; s++) {
                u64 wd = packdup(__ldg(symbol_emb + s * DD + col));
                const float* row = wsT + s * 16 + boff;
#pragma unroll
                for (int p = 0; p < 4; p++)
                    acc[p] = ffma2(*(const u64*)(row + 2 * p), wd, acc[p]);
            }
        } else {
            const int d = col - DD;
#pragma unroll 8
            for (int v = 0; v < VV; v++) {
                u64 wd = packdup(__ldg(value_emb + v * DD + d));
                const float* row = wsT + (64 + v) * 16 + boff;
#pragma unroll
                for (int p = 0; p < 4; p++)
                    acc[p] = ffma2(*(const u64*)(row + 2 * p), wd, acc[p]);
            }
        }
        float* grow = gsT + col * 16 + boff;
#pragma unroll
        for (int p = 0; p < 4; p++) *(u64*)(grow + 2 * p) = acc[p];
    }
    __syncthreads();

    // ---- phase B: h_T[col][bi] = gelu(bias + gs @ W1) ----
    {
        u64 acc[4] = {0ull, 0ull, 0ull, 0ull};
        const float* W1 = (col < DD) ? (oh_W1 + col) : (sf_W1 + col - DD);
#pragma unroll 8
        for (int k = 0; k < 2 * DD; k++) {
            u64 wd = packdup(__ldg(W1 + k * DD));
            const float* row = gsT + k * 16 + boff;
#pragma unroll
            for (int p = 0; p < 4; p++)
                acc[p] = ffma2(*(const u64*)(row + 2 * p), wd, acc[p]);
        }
        float bias = (col < DD) ? oh_b1[col] : sf_b1[col - DD];
        float* hrow = hT + col * 16 + boff;
#pragma unroll
        for (int p = 0; p < 4; p++) {
            float lo, hi;
            asm("mov.b64 {%0,%1}, %2;" : "=f"(lo), "=f"(hi) : "l"(acc[p]));
            hrow[2 * p]     = gelu_fast(lo + bias);
            hrow[2 * p + 1] = gelu_fast(hi + bias);
        }
    }
    __syncthreads();

    // ---- phase C: outputs (col < 96 per half) ----
    if (col < 96) {
        const int j = col;
        u64 acc[4] = {0ull, 0ull, 0ull, 0ull};
        if (j < VV) {
#pragma unroll 8
            for (int k = 0; k < DD; k++) {
                u64 wd = packdup(__ldg(oh_W2 + k * VV + j));
                const float* row = hT + k * 16 + boff;
#pragma unroll
                for (int p = 0; p < 4; p++)
                    acc[p] = ffma2(*(const u64*)(row + 2 * p), wd, acc[p]);
            }
            float bias = oh_b2[j];
#pragma unroll
            for (int p = 0; p < 4; p++) {
                float lo, hi;
                asm("mov.b64 {%0,%1}, %2;" : "=f"(lo), "=f"(hi) : "l"(acc[p]));
                int bi0 = boff + 2 * p;
                int b = b0 + bi0;
                if (bi0 < BPB && b < B)         out[(size_t)b * VV + j] = lo + bias;
                if (bi0 + 1 < BPB && b + 1 < B) out[(size_t)(b + 1) * VV + j] = hi + bias;
            }
        } else {
            const int d = j - VV;
#pragma unroll 8
            for (int k = 0; k < DD; k++) {
                u64 wd = packdup(__ldg(sf_W2 + k * DD + d));
                const float* row = hT + (64 + k) * 16 + boff;
#pragma unroll
                for (int p = 0; p < 4; p++)
                    acc[p] = ffma2(*(const u64*)(row + 2 * p), wd, acc[p]);
            }
            float bias = sf_b2[d];
            float* fb = out + (size_t)B * VV;
#pragma unroll
            for (int p = 0; p < 4; p++) {
                float lo, hi;
                asm("mov.b64 {%0,%1}, %2;" : "=f"(lo), "=f"(hi) : "l"(acc[p]));
                int bi0 = boff + 2 * p;
                int b = b0 + bi0;
                if (bi0 < BPB && b < B)         fb[(size_t)b * DD + d] = lo + bias;
                if (bi0 + 1 < BPB && b + 1 < B) fb[(size_t)(b + 1) * DD + d] = hi + bias;
            }
        }
    }
}

extern "C" void kernel_launch(void* const* d_in, const int* in_sizes, int n_in,
                              void* d_out, int out_size)
{
    const float* evidence    = (const float*)d_in[0];
    const int*   marker      = (const int*)d_in[1];
    const int*   src_idx     = (const int*)d_in[2];
    const int*   src_valid   = (const int*)d_in[3];
    const int*   tsym_idx    = (const int*)d_in[4];
    const int*   tsym_valid  = (const int*)d_in[5];
    const int*   tval_idx    = (const int*)d_in[6];
    const int*   tval_valid  = (const int*)d_in[7];
    const int*   query_idx   = (const int*)d_in[8];
    const int*   query_valid = (const int*)d_in[9];
    const float* symbol_emb  = (const float*)d_in[10];
    const float* value_emb   = (const float*)d_in[11];
    const float* mg_W1 = (const float*)d_in[12];
    const float* mg_b1 = (const float*)d_in[13];
    const float* mg_W2 = (const float*)d_in[14];
    const float* mg_b2 = (const float*)d_in[15];
    const float* sg_W1 = (const float*)d_in[16];
    const float* sg_b1 = (const float*)d_in[17];
    const float* sg_W2 = (const float*)d_in[18];
    const float* sg_b2 = (const float*)d_in[19];
    const float* sf_W1 = (const float*)d_in[20];
    const float* sf_b1 = (const float*)d_in[21];
    const float* sf_W2 = (const float*)d_in[22];
    const float* sf_b2 = (const float*)d_in[23];
    const float* oh_W1 = (const float*)d_in[24];
    const float* oh_b1 = (const float*)d_in[25];
    const float* oh_W2 = (const float*)d_in[26];
    const float* oh_b2 = (const float*)d_in[27];

    const int B = in_sizes[8];

    const int smem = SMEM_FLOATS * (int)sizeof(float);
    cudaFuncSetAttribute(cpm_fused_kernel, cudaFuncAttributeMaxDynamicSharedMemorySize, smem);

    const int grid = (B + BPB - 1) / BPB;
    cpm_fused_kernel<<<grid, 256, smem>>>(
        evidence, marker, src_idx, src_valid, tsym_idx, tsym_valid,
        tval_idx, tval_valid, query_idx, query_valid,
        symbol_emb, value_emb,
        mg_W1, mg_b1, mg_W2, mg_b2,
        sg_W1, sg_b1, sg_W2, sg_b2,
        sf_W1, sf_b1, sf_W2, sf_b2,
        oh_W1, oh_b1, oh_W2, oh_b2,
        (float*)d_out, B);
}

// round 16
// speedup vs baseline: 1.1575x; 1.0238x over previous
#include <cuda_runtime.h>
#include <math.h>

#define TT 256
#define DD 64
#define SS 64
#define VV 32
#define BPB 10           // batches per block -> grid 410 <= 444 = single wave at 3 CTAs/SM
#define LCAP 2560        // packed list capacity (map front, step back); total events <= 2560

typedef unsigned long long u64;

// ---------------- shared layout (floats) ----------------
#define OFF_W1M   0        // 4096 quad-interleaved
#define OFF_W1S   4096     // 4096
#define OFF_B1M   8192     // 64
#define OFF_W2M   8256     // 64
#define OFF_B1S   8320     // 64
#define OFF_W2S   8384     // 64
#define OFF_LIST  8448     // 2560 ints (map front / step back)
#define OFF_GAIN  11008    // 2560 floats (index-aligned with LIST)
#define OFF_X     13568    // 8 warps * 8 tok * 64 = 4096 (gate staging; overlaid later)
#define OFF_CNT   17664    // 2 ints
#define SMEM_FLOATS 17668  // 70672 bytes; 3 CTAs = 212016 <= 228KB

// walk-phase overlay on X region (2240 <= 4096 floats)
#define WX_WALK 0          // 10*64
#define WX_NW   640        // 10*64
#define WX_WSUM 1280       // 10*64
#define WX_ACCV 1920       // 10*32

// heads-tail overlay on LIST+GAIN region (3520 <= 5120 floats), stride-16 rows
#define HT_WS 0            // 96*16  = 1536
#define HT_GS 1536         // 128*16 = 2048  -> needs 3584; LIST+GAIN = 5120 ok
#define HT_H  3584         // 128*16 = 2048 -> 5632 > 5120! adjust: use stride 10? no...

// NOTE: 1536+2048+2048 = 5632 > 5120. Use stride 12 rows instead of 16:
// 96*12 + 128*12 + 128*12 = 4224 <= 5120. boff spans 2*6 batch-slots.
#undef HT_WS
#undef HT_GS
#undef HT_H
#define HTS 12
#define HT_WS 0            // 96*12  = 1152
#define HT_GS 1152         // 128*12 = 1536
#define HT_H  2688         // 128*12 = 1536 -> total 4224 <= 5120

// tanh-form GELU with single-instruction MUFU.TANH.
__device__ __forceinline__ float gelu_fast(float x) {
    float x2 = x * x;
    float inner = x * fmaf(0.044715f, x2, 1.0f);
    float arg = 0.79788456080286535588f * inner;
    float th;
    asm("tanh.approx.f32 %0, %1;" : "=f"(th) : "f"(arg));
    return 0.5f * x * (1.0f + th);
}

__device__ __forceinline__ u64 ffma2(u64 a, u64 b, u64 c) {
    u64 d;
    asm("fma.rn.f32x2 %0, %1, %2, %3;" : "=l"(d) : "l"(a), "l"(b), "l"(c));
    return d;
}
__device__ __forceinline__ u64 packdup(float x) {
    u64 d;
    asm("mov.b64 %0, {%1, %1};" : "=l"(d) : "f"(x));
    return d;
}

// warp-cooperative gate MLP, 8 tokens/pass, lean registers (no pipelining).
// Quad weight layout: Wq[kq*256 + f*4 + j] = W[4kq+j][f]
// item: tok[0:8) | bi[8:12) | src[12:18) | tgt[18:24)
// Epilogue: multi-token butterfly reduction — 8 sums in 9 shfls.
__device__ __forceinline__ void process_events8(
    const int* __restrict__ list, int n, float b2,
    float* __restrict__ gout,
    const float* __restrict__ sWq, const float* __restrict__ sb1,
    const float* __restrict__ sw2,
    const float* __restrict__ evidence, int b0,
    float* __restrict__ sXw, int lane)
{
    const int wid = threadIdx.x >> 5;
    const int sel = lane >> 4;           // 0: even token of pair, 1: odd
    const int sub = lane & 15;           // 16B chunk within row
    const int sel16 = (lane >> 4) & 1;
    const int sel8  = (lane >> 3) & 1;
    const int sel4  = (lane >> 2) & 1;
    const int tok_id = lane >> 2;
    const bool writer = (lane & 3) == 0;

    const float b1a = sb1[lane], b1b = sb1[lane + 32];
    const float w2a = sw2[lane], w2b = sw2[lane + 32];

    for (int base = wid * 8; base < n; base += 64) {
        // gather 8 evidence rows straight into the staging buffer
#pragma unroll
        for (int i = 0; i < 8; i += 2) {
            int idx = base + i + sel;
            int it = list[(idx < n) ? idx : (n - 1)];
            int tok = it & 255;
            int bb  = (it >> 8) & 15;
            float4 v = *((const float4*)(evidence + ((size_t)(b0 + bb) * TT + tok) * DD) + sub);
            *(float4*)(sXw + (i + sel) * DD + sub * 4) = v;
        }
        __syncwarp();

        u64 acc0[8], acc1[8];
#pragma unroll
        for (int i = 0; i < 8; i++) { acc0[i] = 0ull; acc1[i] = 0ull; }

#pragma unroll
        for (int kq = 0; kq < DD / 4; kq++) {
            ulonglong2 wa = *(const ulonglong2*)(sWq + kq * 256 + 4 * lane);        // feat l
            ulonglong2 wb = *(const ulonglong2*)(sWq + kq * 256 + 128 + 4 * lane);  // feat l+32
#pragma unroll
            for (int i = 0; i < 8; i++) {
                ulonglong2 xq = *(const ulonglong2*)(sXw + i * DD + 4 * kq);  // broadcast LDS.128
                acc0[i] = ffma2(xq.x, wa.x, acc0[i]);
                acc0[i] = ffma2(xq.y, wa.y, acc0[i]);
                acc1[i] = ffma2(xq.x, wb.x, acc1[i]);
                acc1[i] = ffma2(xq.y, wb.y, acc1[i]);
            }
        }

        float p[8];
#pragma unroll
        for (int i = 0; i < 8; i++) {
            float lo, hi;
            asm("mov.b64 {%0,%1}, %2;" : "=f"(lo), "=f"(hi) : "l"(acc0[i]));
            float h0 = lo + hi + b1a;
            asm("mov.b64 {%0,%1}, %2;" : "=f"(lo), "=f"(hi) : "l"(acc1[i]));
            float h1 = lo + hi + b1b;
            p[i] = gelu_fast(h0) * w2a + gelu_fast(h1) * w2b;
        }

        // multi-token fold: 9 shfls total.
        float q[4];
#pragma unroll
        for (int j = 0; j < 4; j++) {
            float snd = sel16 ? p[j] : p[j + 4];
            float kp  = sel16 ? p[j + 4] : p[j];
            q[j] = kp + __shfl_xor_sync(0xffffffffu, snd, 16);
        }
        float r[2];
#pragma unroll
        for (int j = 0; j < 2; j++) {
            float snd = sel8 ? q[j] : q[j + 2];
            float kp  = sel8 ? q[j + 2] : q[j];
            r[j] = kp + __shfl_xor_sync(0xffffffffu, snd, 8);
        }
        float s;
        {
            float snd = sel4 ? r[0] : r[1];
            float kp  = sel4 ? r[1] : r[0];
            s = kp + __shfl_xor_sync(0xffffffffu, snd, 4);
        }
        s += __shfl_xor_sync(0xffffffffu, s, 2);
        s += __shfl_xor_sync(0xffffffffu, s, 1);

        if (writer) {
            int idx = base + tok_id;
            if (idx < n)
                gout[idx] = 1.0f / (1.0f + __expf(-(s + b2)));
        }
        __syncwarp();
    }
}

__global__ __launch_bounds__(256, 3)
void cpm_fused_kernel(
    const float* __restrict__ evidence,
    const int* __restrict__ marker,
    const int* __restrict__ src_idx,
    const int* __restrict__ src_valid,
    const int* __restrict__ tsym_idx,
    const int* __restrict__ tsym_valid,
    const int* __restrict__ tval_idx,
    const int* __restrict__ tval_valid,
    const int* __restrict__ query_idx,
    const int* __restrict__ query_valid,
    const float* __restrict__ symbol_emb,
    const float* __restrict__ value_emb,
    const float* __restrict__ mg_W1, const float* __restrict__ mg_b1,
    const float* __restrict__ mg_W2, const float* __restrict__ mg_b2,
    const float* __restrict__ sg_W1, const float* __restrict__ sg_b1,
    const float* __restrict__ sg_W2, const float* __restrict__ sg_b2,
    const float* __restrict__ sf_W1, const float* __restrict__ sf_b1,
    const float* __restrict__ sf_W2, const float* __restrict__ sf_b2,
    const float* __restrict__ oh_W1, const float* __restrict__ oh_b1,
    const float* __restrict__ oh_W2, const float* __restrict__ oh_b2,
    float* __restrict__ out, int B)
{
    extern __shared__ float sm[];
    float* sW1m  = sm + OFF_W1M;
    float* sW1s  = sm + OFF_W1S;
    float* sb1m  = sm + OFF_B1M;
    float* sw2m  = sm + OFF_W2M;
    float* sb1s  = sm + OFF_B1S;
    float* sw2s  = sm + OFF_W2S;
    int*   sList = (int*)(sm + OFF_LIST);
    float* sGain = sm + OFF_GAIN;
    float* sX    = sm + OFF_X;
    int*   sCnt  = (int*)(sm + OFF_CNT);

    const int tid  = threadIdx.x;
    const int lane = tid & 31;
    const int wid  = tid >> 5;
    const int b0   = blockIdx.x * BPB;

    if (tid < 2) sCnt[tid] = 0;
    __syncthreads();

    // build packed compact event lists (map from front, step from back)
#pragma unroll
    for (int bi = 0; bi < BPB; bi++) {
        const int b = b0 + bi;
        if (b >= B) break;
        const int gt = b * TT + tid;
        int m  = marker[gt];
        int sv = src_valid[gt];
        if (sv != 0) {
            int si = min(max(src_idx[gt], 0), SS - 1);
            if (m == 1 || m == 2) {
                if (tval_valid[gt] != 0) {
                    int tv = min(max(tval_idx[gt], 0), VV - 1);
                    int p = atomicAdd(&sCnt[0], 1);
                    sList[p] = tid | (bi << 8) | (si << 12) | (tv << 18);
                }
            } else if (m == 3) {
                if (tsym_valid[gt] != 0) {
                    int ts = min(max(tsym_idx[gt], 0), SS - 1);
                    int p = atomicAdd(&sCnt[1], 1);
                    sList[LCAP - 1 - p] = tid | (bi << 8) | (si << 12) | (ts << 18);
                }
            }
        }
    }

    // stage gate weights, k-quad interleaved (plain LDG->STS)
    for (int i = tid; i < DD * DD; i += 256) {
        int k = i >> 6, f = i & 63;
        int dst = (k >> 2) * 256 + (f << 2) + (k & 3);
        sW1m[dst] = mg_W1[i];
        sW1s[dst] = sg_W1[i];
    }
    if (tid < DD) {
        sb1m[tid] = mg_b1[tid]; sw2m[tid] = mg_W2[tid];
        sb1s[tid] = sg_b1[tid]; sw2s[tid] = sg_W2[tid];
    }
    __syncthreads();

    const int nmap  = sCnt[0];
    const int nstep = sCnt[1];
    const int*   lstep = sList + LCAP - nstep;
    float*       gstep = sGain + LCAP - nstep;
    float* sXw = sX + wid * 8 * DD;

    process_events8(sList, nmap, mg_b2[0], sGain, sW1m, sb1m, sw2m,
                    evidence, b0, sXw, lane);
    process_events8(lstep, nstep, sg_b2[0], gstep, sW1s, sb1s, sw2s,
                    evidence, b0, sXw, lane);
    __syncthreads();

    // ---- sparse walk: overlay on X region; warps cover 10 batches in two rounds ----
    float* sWalk = sX + WX_WALK;
    float* sNw   = sX + WX_NW;
    float* sWsum = sX + WX_WSUM;
    float* sAccv = sX + WX_ACCV;
#pragma unroll
    for (int ph = 0; ph < 2; ph++) {
        const int bi = wid + ph * 8;
        if (bi < BPB) {
            const int b = b0 + bi;
            float* walk = sWalk + bi * SS;
            float* nw   = sNw   + bi * SS;
            float* wsum = sWsum + bi * SS;
            float* accv = sAccv + bi * VV;
            if (b < B) {
                int q = min(max(query_idx[b], 0), SS - 1);
                float qv = (float)query_valid[b];
#pragma unroll
                for (int i = lane; i < SS; i += 32) {
                    float w = (i == q) ? qv : 0.f;
                    walk[i] = w; wsum[i] = w;
                }
                if (lane < VV) accv[lane] = 0.f;
                __syncwarp();

                for (int it = 0; it < 3; it++) {
#pragma unroll
                    for (int i = lane; i < SS; i += 32) nw[i] = 0.f;
                    __syncwarp();
                    for (int e = lane; e < nstep; e += 32) {
                        int item = lstep[e];
                        if (((item >> 8) & 15) == bi) {
                            int src = (item >> 12) & 63;
                            int tgt = (item >> 18) & 63;
                            atomicAdd(&nw[tgt], gstep[e] * walk[src]);
                        }
                    }
                    __syncwarp();
#pragma unroll
                    for (int i = lane; i < SS; i += 32) {
                        float w = nw[i];
                        walk[i] = w; wsum[i] += w;
                    }
                    __syncwarp();
                }
                for (int e = lane; e < nmap; e += 32) {
                    int item = sList[e];
                    if (((item >> 8) & 15) == bi) {
                        int src = (item >> 12) & 63;
                        int tv  = (item >> 18) & 63;
                        atomicAdd(&accv[tv], sGain[e] * wsum[src]);
                    }
                }
            } else {
                if (lane < VV) accv[lane] = 0.f;
#pragma unroll
                for (int i = lane; i < SS; i += 32) wsum[i] = 0.f;
            }
        }
    }
    __syncthreads();

    // ==== fused heads: overlay transposed states on dead list/gain region ====
    float* wsT = sm + OFF_LIST + HT_WS;   // [96][12]
    float* gsT = sm + OFF_LIST + HT_GS;   // [128][12]
    float* hT  = sm + OFF_LIST + HT_H;    // [128][12]

    for (int idx = tid; idx < 96 * HTS; idx += 256) {
        int j = idx / HTS, bi = idx - j * HTS;
        float v = 0.f;
        if (bi < BPB)
            v = (j < 64) ? sWsum[bi * SS + j] : sAccv[bi * VV + (j - 64)];
        wsT[j * HTS + bi] = v;
    }
    __syncthreads();

    const int col  = tid & 127;
    const int half = tid >> 7;          // 6 batch-slots per half
    const int boff = half * 6;

    // ---- phase A: gs_T[col][bi] ----
    {
        u64 acc[3] = {0ull, 0ull, 0ull};
        if (col < DD) {
#pragma unroll 8
            for (int s = 0; s < SS; s++) {
                u64 wd = packdup(__ldg(symbol_emb + s * DD + col));
                const float* row = wsT + s * HTS + boff;
#pragma unroll
                for (int p = 0; p < 3; p++)
                    acc[p] = ffma2(*(const u64*)(row + 2 * p), wd, acc[p]);
            }
        } else {
            const int d = col - DD;
#pragma unroll 8
            for (int v = 0; v < VV; v++) {
                u64 wd = packdup(__ldg(value_emb + v * DD + d));
                const float* row = wsT + (64 + v) * HTS + boff;
#pragma unroll
                for (int p = 0; p < 3; p++)
                    acc[p] = ffma2(*(const u64*)(row + 2 * p), wd, acc[p]);
            }
        }
        float* grow = gsT + col * HTS + boff;
#pragma unroll
        for (int p = 0; p < 3; p++) *(u64*)(grow + 2 * p) = acc[p];
    }
    __syncthreads();

    // ---- phase B: h_T[col][bi] = gelu(bias + gs @ W1) ----
    {
        u64 acc[3] = {0ull, 0ull, 0ull};
        const float* W1 = (col < DD) ? (oh_W1 + col) : (sf_W1 + col - DD);
#pragma unroll 8
        for (int k = 0; k < 2 * DD; k++) {
            u64 wd = packdup(__ldg(W1 + k * DD));
            const float* row = gsT + k * HTS + boff;
#pragma unroll
            for (int p = 0; p < 3; p++)
                acc[p] = ffma2(*(const u64*)(row + 2 * p), wd, acc[p]);
        }
        float bias = (col < DD) ? oh_b1[col] : sf_b1[col - DD];
        float* hrow = hT + col * HTS + boff;
#pragma unroll
        for (int p = 0; p < 3; p++) {
            float lo, hi;
            asm("mov.b64 {%0,%1}, %2;" : "=f"(lo), "=f"(hi) : "l"(acc[p]));
            hrow[2 * p]     = gelu_fast(lo + bias);
            hrow[2 * p + 1] = gelu_fast(hi + bias);
        }
    }
    __syncthreads();

    // ---- phase C: outputs (col < 96 per half) ----
    if (col < 96) {
        const int j = col;
        u64 acc[3] = {0ull, 0ull, 0ull};
        if (j < VV) {
#pragma unroll 8
            for (int k = 0; k < DD; k++) {
                u64 wd = packdup(__ldg(oh_W2 + k * VV + j));
                const float* row = hT + k * HTS + boff;
#pragma unroll
                for (int p = 0; p < 3; p++)
                    acc[p] = ffma2(*(const u64*)(row + 2 * p), wd, acc[p]);
            }
            float bias = oh_b2[j];
#pragma unroll
            for (int p = 0; p < 3; p++) {
                float lo, hi;
                asm("mov.b64 {%0,%1}, %2;" : "=f"(lo), "=f"(hi) : "l"(acc[p]));
                int bi0 = boff + 2 * p;
                int b = b0 + bi0;
                if (bi0 < BPB && b < B)         out[(size_t)b * VV + j] = lo + bias;
                if (bi0 + 1 < BPB && b + 1 < B) out[(size_t)(b + 1) * VV + j] = hi + bias;
            }
        } else {
            const int d = j - VV;
#pragma unroll 8
            for (int k = 0; k < DD; k++) {
                u64 wd = packdup(__ldg(sf_W2 + k * DD + d));
                const float* row = hT + (64 + k) * HTS + boff;
#pragma unroll
                for (int p = 0; p < 3; p++)
                    acc[p] = ffma2(*(const u64*)(row + 2 * p), wd, acc[p]);
            }
            float bias = sf_b2[d];
            float* fb = out + (size_t)B * VV;
#pragma unroll
            for (int p = 0; p < 3; p++) {
                float lo, hi;
                asm("mov.b64 {%0,%1}, %2;" : "=f"(lo), "=f"(hi) : "l"(acc[p]));
                int bi0 = boff + 2 * p;
                int b = b0 + bi0;
                if (bi0 < BPB && b < B)         fb[(size_t)b * DD + d] = lo + bias;
                if (bi0 + 1 < BPB && b + 1 < B) fb[(size_t)(b + 1) * DD + d] = hi + bias;
            }
        }
    }
}

extern "C" void kernel_launch(void* const* d_in, const int* in_sizes, int n_in,
                              void* d_out, int out_size)
{
    const float* evidence    = (const float*)d_in[0];
    const int*   marker      = (const int*)d_in[1];
    const int*   src_idx     = (const int*)d_in[2];
    const int*   src_valid   = (const int*)d_in[3];
    const int*   tsym_idx    = (const int*)d_in[4];
    const int*   tsym_valid  = (const int*)d_in[5];
    const int*   tval_idx    = (const int*)d_in[6];
    const int*   tval_valid  = (const int*)d_in[7];
    const int*   query_idx   = (const int*)d_in[8];
    const int*   query_valid = (const int*)d_in[9];
    const float* symbol_emb  = (const float*)d_in[10];
    const float* value_emb   = (const float*)d_in[11];
    const float* mg_W1 = (const float*)d_in[12];
    const float* mg_b1 = (const float*)d_in[13];
    const float* mg_W2 = (const float*)d_in[14];
    const float* mg_b2 = (const float*)d_in[15];
    const float* sg_W1 = (const float*)d_in[16];
    const float* sg_b1 = (const float*)d_in[17];
    const float* sg_W2 = (const float*)d_in[18];
    const float* sg_b2 = (const float*)d_in[19];
    const float* sf_W1 = (const float*)d_in[20];
    const float* sf_b1 = (const float*)d_in[21];
    const float* sf_W2 = (const float*)d_in[22];
    const float* sf_b2 = (const float*)d_in[23];
    const float* oh_W1 = (const float*)d_in[24];
    const float* oh_b1 = (const float*)d_in[25];
    const float* oh_W2 = (const float*)d_in[26];
    const float* oh_b2 = (const float*)d_in[27];

    const int B = in_sizes[8];

    const int smem = SMEM_FLOATS * (int)sizeof(float);
    cudaFuncSetAttribute(cpm_fused_kernel, cudaFuncAttributeMaxDynamicSharedMemorySize, smem);

    const int grid = (B + BPB - 1) / BPB;
    cpm_fused_kernel<<<grid, 256, smem>>>(
        evidence, marker, src_idx, src_valid, tsym_idx, tsym_valid,
        tval_idx, tval_valid, query_idx, query_valid,
        symbol_emb, value_emb,
        mg_W1, mg_b1, mg_W2, mg_b2,
        sg_W1, sg_b1, sg_W2, sg_b2,
        sf_W1, sf_b1, sf_W2, sf_b2,
        oh_W1, oh_b1, oh_W2, oh_b2,
        (float*)d_out, B);
}

// round 17
// speedup vs baseline: 1.2106x; 1.0459x over previous
#include <cuda_runtime.h>
#include <math.h>

#define TT 256
#define DD 64
#define SS 64
#define VV 32
#define BPB 10           // batches per block -> grid 410 <= 444 = single wave at 3 CTAs/SM
#define LCAP 2560        // packed list capacity (map front, step back)

typedef unsigned long long u64;

// ---------------- shared layout (floats) ----------------
#define OFF_W1M   0        // 4096 quad-interleaved
#define OFF_W1S   4096     // 4096
#define OFF_B1M   8192     // 64
#define OFF_W2M   8256     // 64
#define OFF_B1S   8320     // 64
#define OFF_W2S   8384     // 64
#define OFF_LIST  8448     // 2560 ints (map front / step back)
#define OFF_GAIN  11008    // 2560 floats (index-aligned with LIST)
#define OFF_X     13568    // 8 warps * 8 tok * 64 = 4096 (gate staging; overlaid later)
#define OFF_CNT   17664    // 2 ints
#define SMEM_FLOATS 17668  // 70672 bytes; 3 CTAs = 212016 <= 228KB

// walk-phase overlay on X region (2240 <= 4096 floats)
#define WX_WALK 0          // 10*64
#define WX_NW   640        // 10*64
#define WX_WSUM 1280       // 10*64
#define WX_ACCV 1920       // 10*32

// heads-tail overlay on LIST+GAIN region, stride-12 batch rows (4224 <= 5120)
#define HTS 12
#define HT_WS 0            // 96*12  = 1152
#define HT_GS 1152         // 128*12 = 1536
#define HT_H  2688         // 128*12 = 1536

// tanh-form GELU with single-instruction MUFU.TANH.
__device__ __forceinline__ float gelu_fast(float x) {
    float x2 = x * x;
    float inner = x * fmaf(0.044715f, x2, 1.0f);
    float arg = 0.79788456080286535588f * inner;
    float th;
    asm("tanh.approx.f32 %0, %1;" : "=f"(th) : "f"(arg));
    return 0.5f * x * (1.0f + th);
}

__device__ __forceinline__ u64 ffma2(u64 a, u64 b, u64 c) {
    u64 d;
    asm("fma.rn.f32x2 %0, %1, %2, %3;" : "=l"(d) : "l"(a), "l"(b), "l"(c));
    return d;
}
__device__ __forceinline__ u64 packdup(float x) {
    u64 d;
    asm("mov.b64 %0, {%1, %1};" : "=l"(d) : "f"(x));
    return d;
}

// warp-cooperative gate MLP, 8 tokens/pass, lean registers.
// Quad weight layout: Wq[kq*256 + f*4 + j] = W[4kq+j][f]
// item: tok[0:8) | bi[8:12) | src[12:18) | tgt[18:24)
// Epilogue: multi-token butterfly reduction — 8 sums in 9 shfls.
__device__ __forceinline__ void process_events8(
    const int* __restrict__ list, int n, float b2,
    float* __restrict__ gout,
    const float* __restrict__ sWq, const float* __restrict__ sb1,
    const float* __restrict__ sw2,
    const float* __restrict__ evidence, int b0,
    float* __restrict__ sXw, int lane)
{
    const int wid = threadIdx.x >> 5;
    const int sel = lane >> 4;           // 0: even token of pair, 1: odd
    const int sub = lane & 15;           // 16B chunk within row
    const int sel16 = (lane >> 4) & 1;
    const int sel8  = (lane >> 3) & 1;
    const int sel4  = (lane >> 2) & 1;
    const int tok_id = lane >> 2;
    const bool writer = (lane & 3) == 0;

    const float b1a = sb1[lane], b1b = sb1[lane + 32];
    const float w2a = sw2[lane], w2b = sw2[lane + 32];

    for (int base = wid * 8; base < n; base += 64) {
        // gather 8 evidence rows straight into the staging buffer
#pragma unroll
        for (int i = 0; i < 8; i += 2) {
            int idx = base + i + sel;
            int it = list[(idx < n) ? idx : (n - 1)];
            int tok = it & 255;
            int bb  = (it >> 8) & 15;
            float4 v = *((const float4*)(evidence + ((size_t)(b0 + bb) * TT + tok) * DD) + sub);
            *(float4*)(sXw + (i + sel) * DD + sub * 4) = v;
        }
        __syncwarp();

        u64 acc0[8], acc1[8];
#pragma unroll
        for (int i = 0; i < 8; i++) { acc0[i] = 0ull; acc1[i] = 0ull; }

#pragma unroll
        for (int kq = 0; kq < DD / 4; kq++) {
            ulonglong2 wa = *(const ulonglong2*)(sWq + kq * 256 + 4 * lane);        // feat l
            ulonglong2 wb = *(const ulonglong2*)(sWq + kq * 256 + 128 + 4 * lane);  // feat l+32
#pragma unroll
            for (int i = 0; i < 8; i++) {
                ulonglong2 xq = *(const ulonglong2*)(sXw + i * DD + 4 * kq);  // broadcast LDS.128
                acc0[i] = ffma2(xq.x, wa.x, acc0[i]);
                acc0[i] = ffma2(xq.y, wa.y, acc0[i]);
                acc1[i] = ffma2(xq.x, wb.x, acc1[i]);
                acc1[i] = ffma2(xq.y, wb.y, acc1[i]);
            }
        }

        float p[8];
#pragma unroll
        for (int i = 0; i < 8; i++) {
            float lo, hi;
            asm("mov.b64 {%0,%1}, %2;" : "=f"(lo), "=f"(hi) : "l"(acc0[i]));
            float h0 = lo + hi + b1a;
            asm("mov.b64 {%0,%1}, %2;" : "=f"(lo), "=f"(hi) : "l"(acc1[i]));
            float h1 = lo + hi + b1b;
            p[i] = gelu_fast(h0) * w2a + gelu_fast(h1) * w2b;
        }

        // multi-token fold: 9 shfls total.
        float q[4];
#pragma unroll
        for (int j = 0; j < 4; j++) {
            float snd = sel16 ? p[j] : p[j + 4];
            float kp  = sel16 ? p[j + 4] : p[j];
            q[j] = kp + __shfl_xor_sync(0xffffffffu, snd, 16);
        }
        float r[2];
#pragma unroll
        for (int j = 0; j < 2; j++) {
            float snd = sel8 ? q[j] : q[j + 2];
            float kp  = sel8 ? q[j + 2] : q[j];
            r[j] = kp + __shfl_xor_sync(0xffffffffu, snd, 8);
        }
        float s;
        {
            float snd = sel4 ? r[0] : r[1];
            float kp  = sel4 ? r[1] : r[0];
            s = kp + __shfl_xor_sync(0xffffffffu, snd, 4);
        }
        s += __shfl_xor_sync(0xffffffffu, s, 2);
        s += __shfl_xor_sync(0xffffffffu, s, 1);

        if (writer) {
            int idx = base + tok_id;
            if (idx < n)
                gout[idx] = 1.0f / (1.0f + __expf(-(s + b2)));
        }
        __syncwarp();
    }
}

__global__ __launch_bounds__(256, 3)
void cpm_fused_kernel(
    const float* __restrict__ evidence,
    const int* __restrict__ marker,
    const int* __restrict__ src_idx,
    const int* __restrict__ src_valid,
    const int* __restrict__ tsym_idx,
    const int* __restrict__ tsym_valid,
    const int* __restrict__ tval_idx,
    const int* __restrict__ tval_valid,
    const int* __restrict__ query_idx,
    const int* __restrict__ query_valid,
    const float* __restrict__ symbol_emb,
    const float* __restrict__ value_emb,
    const float* __restrict__ mg_W1, const float* __restrict__ mg_b1,
    const float* __restrict__ mg_W2, const float* __restrict__ mg_b2,
    const float* __restrict__ sg_W1, const float* __restrict__ sg_b1,
    const float* __restrict__ sg_W2, const float* __restrict__ sg_b2,
    const float* __restrict__ sf_W1, const float* __restrict__ sf_b1,
    const float* __restrict__ sf_W2, const float* __restrict__ sf_b2,
    const float* __restrict__ oh_W1, const float* __restrict__ oh_b1,
    const float* __restrict__ oh_W2, const float* __restrict__ oh_b2,
    float* __restrict__ out, int B)
{
    extern __shared__ float sm[];
    float* sW1m  = sm + OFF_W1M;
    float* sW1s  = sm + OFF_W1S;
    float* sb1m  = sm + OFF_B1M;
    float* sw2m  = sm + OFF_W2M;
    float* sb1s  = sm + OFF_B1S;
    float* sw2s  = sm + OFF_W2S;
    int*   sList = (int*)(sm + OFF_LIST);
    float* sGain = sm + OFF_GAIN;
    float* sX    = sm + OFF_X;
    int*   sCnt  = (int*)(sm + OFF_CNT);

    const int tid  = threadIdx.x;
    const int lane = tid & 31;
    const int wid  = tid >> 5;
    const int b0   = blockIdx.x * BPB;

    if (tid < 2) sCnt[tid] = 0;
    __syncthreads();

    // prefetch marker + src_valid for all batches (one latency exposure)
    int m_[BPB], sv_[BPB];
#pragma unroll
    for (int bi = 0; bi < BPB; bi++) {
        int b = b0 + bi;
        int gt = (b < B ? b : B - 1) * TT + tid;
        m_[bi]  = marker[gt];
        sv_[bi] = (b < B) ? src_valid[gt] : 0;
    }

    // build packed compact event lists (map from front, step from back)
#pragma unroll
    for (int bi = 0; bi < BPB; bi++) {
        if (sv_[bi] != 0) {
            const int gt = (b0 + bi) * TT + tid;
            int m = m_[bi];
            if (m == 1 || m == 2) {
                if (tval_valid[gt] != 0) {
                    int si = min(max(src_idx[gt], 0), SS - 1);
                    int tv = min(max(tval_idx[gt], 0), VV - 1);
                    int p = atomicAdd(&sCnt[0], 1);
                    sList[p] = tid | (bi << 8) | (si << 12) | (tv << 18);
                }
            } else if (m == 3) {
                if (tsym_valid[gt] != 0) {
                    int si = min(max(src_idx[gt], 0), SS - 1);
                    int ts = min(max(tsym_idx[gt], 0), SS - 1);
                    int p = atomicAdd(&sCnt[1], 1);
                    sList[LCAP - 1 - p] = tid | (bi << 8) | (si << 12) | (ts << 18);
                }
            }
        }
    }

    // stage gate weights, k-quad interleaved (plain LDG->STS)
    for (int i = tid; i < DD * DD; i += 256) {
        int k = i >> 6, f = i & 63;
        int dst = (k >> 2) * 256 + (f << 2) + (k & 3);
        sW1m[dst] = mg_W1[i];
        sW1s[dst] = sg_W1[i];
    }
    if (tid < DD) {
        sb1m[tid] = mg_b1[tid]; sw2m[tid] = mg_W2[tid];
        sb1s[tid] = sg_b1[tid]; sw2s[tid] = sg_W2[tid];
    }
    __syncthreads();

    const int nmap  = sCnt[0];
    const int nstep = sCnt[1];
    const int*   lstep = sList + LCAP - nstep;
    float*       gstep = sGain + LCAP - nstep;
    float* sXw = sX + wid * 8 * DD;

    process_events8(sList, nmap, mg_b2[0], sGain, sW1m, sb1m, sw2m,
                    evidence, b0, sXw, lane);
    process_events8(lstep, nstep, sg_b2[0], gstep, sW1s, sb1s, sw2s,
                    evidence, b0, sXw, lane);
    __syncthreads();

    // ---- sparse walk: one half-warp per batch, single parallel round ----
    float* sWalk = sX + WX_WALK;
    float* sNw   = sX + WX_NW;
    float* sWsum = sX + WX_WSUM;
    float* sAccv = sX + WX_ACCV;
    {
        const int hw  = tid >> 4;        // half-warp id, 0..15
        const int l16 = tid & 15;
        if (hw < BPB) {
            const int bi = hw;
            const int b = b0 + bi;
            float* walk = sWalk + bi * SS;
            float* nw   = sNw   + bi * SS;
            float* wsum = sWsum + bi * SS;
            float* accv = sAccv + bi * VV;

            // uniform path: invalid batches run with qv=0 (no events exist for them)
            int q = 0; float qv = 0.f;
            if (b < B) {
                q  = min(max(query_idx[b], 0), SS - 1);
                qv = (float)query_valid[b];
            }
#pragma unroll
            for (int i = l16; i < SS; i += 16) {
                float w = (i == q) ? qv : 0.f;
                walk[i] = w; wsum[i] = w;
            }
#pragma unroll
            for (int i = l16; i < VV; i += 16) accv[i] = 0.f;
            __syncwarp();

            for (int it = 0; it < 3; it++) {
#pragma unroll
                for (int i = l16; i < SS; i += 16) nw[i] = 0.f;
                __syncwarp();
                for (int e = l16; e < nstep; e += 16) {
                    int item = lstep[e];
                    if (((item >> 8) & 15) == bi) {
                        int src = (item >> 12) & 63;
                        int tgt = (item >> 18) & 63;
                        atomicAdd(&nw[tgt], gstep[e] * walk[src]);
                    }
                }
                __syncwarp();
#pragma unroll
                for (int i = l16; i < SS; i += 16) {
                    float w = nw[i];
                    walk[i] = w; wsum[i] += w;
                }
                __syncwarp();
            }
            for (int e = l16; e < nmap; e += 16) {
                int item = sList[e];
                if (((item >> 8) & 15) == bi) {
                    int src = (item >> 12) & 63;
                    int tv  = (item >> 18) & 63;
                    atomicAdd(&accv[tv], sGain[e] * wsum[src]);
                }
            }
        }
    }
    __syncthreads();

    // ==== fused heads: overlay transposed states on dead list/gain region ====
    float* wsT = sm + OFF_LIST + HT_WS;   // [96][12]
    float* gsT = sm + OFF_LIST + HT_GS;   // [128][12]
    float* hT  = sm + OFF_LIST + HT_H;    // [128][12]

    for (int idx = tid; idx < 96 * HTS; idx += 256) {
        int j = idx / HTS, bi = idx - j * HTS;
        float v = 0.f;
        if (bi < BPB)
            v = (j < 64) ? sWsum[bi * SS + j] : sAccv[bi * VV + (j - 64)];
        wsT[j * HTS + bi] = v;
    }
    __syncthreads();

    const int col  = tid & 127;
    const int half = tid >> 7;          // 6 batch-slots per half
    const int boff = half * 6;

    // ---- phase A: gs_T[col][bi] ----
    {
        u64 acc[3] = {0ull, 0ull, 0ull};
        if (col < DD) {
#pragma unroll 8
            for (int s = 0; s < SS; s++) {
                u64 wd = packdup(__ldg(symbol_emb + s * DD + col));
                const float* row = wsT + s * HTS + boff;
#pragma unroll
                for (int p = 0; p < 3; p++)
                    acc[p] = ffma2(*(const u64*)(row + 2 * p), wd, acc[p]);
            }
        } else {
            const int d = col - DD;
#pragma unroll 8
            for (int v = 0; v < VV; v++) {
                u64 wd = packdup(__ldg(value_emb + v * DD + d));
                const float* row = wsT + (64 + v) * HTS + boff;
#pragma unroll
                for (int p = 0; p < 3; p++)
                    acc[p] = ffma2(*(const u64*)(row + 2 * p), wd, acc[p]);
            }
        }
        float* grow = gsT + col * HTS + boff;
#pragma unroll
        for (int p = 0; p < 3; p++) *(u64*)(grow + 2 * p) = acc[p];
    }
    __syncthreads();

    // ---- phase B: h_T[col][bi] = gelu(bias + gs @ W1) ----
    {
        u64 acc[3] = {0ull, 0ull, 0ull};
        const float* W1 = (col < DD) ? (oh_W1 + col) : (sf_W1 + col - DD);
#pragma unroll 8
        for (int k = 0; k < 2 * DD; k++) {
            u64 wd = packdup(__ldg(W1 + k * DD));
            const float* row = gsT + k * HTS + boff;
#pragma unroll
            for (int p = 0; p < 3; p++)
                acc[p] = ffma2(*(const u64*)(row + 2 * p), wd, acc[p]);
        }
        float bias = (col < DD) ? oh_b1[col] : sf_b1[col - DD];
        float* hrow = hT + col * HTS + boff;
#pragma unroll
        for (int p = 0; p < 3; p++) {
            float lo, hi;
            asm("mov.b64 {%0,%1}, %2;" : "=f"(lo), "=f"(hi) : "l"(acc[p]));
            hrow[2 * p]     = gelu_fast(lo + bias);
            hrow[2 * p + 1] = gelu_fast(hi + bias);
        }
    }
    __syncthreads();

    // ---- phase C: outputs (col < 96 per half) ----
    if (col < 96) {
        const int j = col;
        u64 acc[3] = {0ull, 0ull, 0ull};
        if (j < VV) {
#pragma unroll 8
            for (int k = 0; k < DD; k++) {
                u64 wd = packdup(__ldg(oh_W2 + k * VV + j));
                const float* row = hT + k * HTS + boff;
#pragma unroll
                for (int p = 0; p < 3; p++)
                    acc[p] = ffma2(*(const u64*)(row + 2 * p), wd, acc[p]);
            }
            float bias = oh_b2[j];
#pragma unroll
            for (int p = 0; p < 3; p++) {
                float lo, hi;
                asm("mov.b64 {%0,%1}, %2;" : "=f"(lo), "=f"(hi) : "l"(acc[p]));
                int bi0 = boff + 2 * p;
                int b = b0 + bi0;
                if (bi0 < BPB && b < B)         out[(size_t)b * VV + j] = lo + bias;
                if (bi0 + 1 < BPB && b + 1 < B) out[(size_t)(b + 1) * VV + j] = hi + bias;
            }
        } else {
            const int d = j - VV;
#pragma unroll 8
            for (int k = 0; k < DD; k++) {
                u64 wd = packdup(__ldg(sf_W2 + k * DD + d));
                const float* row = hT + (64 + k) * HTS + boff;
#pragma unroll
                for (int p = 0; p < 3; p++)
                    acc[p] = ffma2(*(const u64*)(row + 2 * p), wd, acc[p]);
            }
            float bias = sf_b2[d];
            float* fb = out + (size_t)B * VV;
#pragma unroll
            for (int p = 0; p < 3; p++) {
                float lo, hi;
                asm("mov.b64 {%0,%1}, %2;" : "=f"(lo), "=f"(hi) : "l"(acc[p]));
                int bi0 = boff + 2 * p;
                int b = b0 + bi0;
                if (bi0 < BPB && b < B)         fb[(size_t)b * DD + d] = lo + bias;
                if (bi0 + 1 < BPB && b + 1 < B) fb[(size_t)(b + 1) * DD + d] = hi + bias;
            }
        }
    }
}

extern "C" void kernel_launch(void* const* d_in, const int* in_sizes, int n_in,
                              void* d_out, int out_size)
{
    const float* evidence    = (const float*)d_in[0];
    const int*   marker      = (const int*)d_in[1];
    const int*   src_idx     = (const int*)d_in[2];
    const int*   src_valid   = (const int*)d_in[3];
    const int*   tsym_idx    = (const int*)d_in[4];
    const int*   tsym_valid  = (const int*)d_in[5];
    const int*   tval_idx    = (const int*)d_in[6];
    const int*   tval_valid  = (const int*)d_in[7];
    const int*   query_idx   = (const int*)d_in[8];
    const int*   query_valid = (const int*)d_in[9];
    const float* symbol_emb  = (const float*)d_in[10];
    const float* value_emb   = (const float*)d_in[11];
    const float* mg_W1 = (const float*)d_in[12];
    const float* mg_b1 = (const float*)d_in[13];
    const float* mg_W2 = (const float*)d_in[14];
    const float* mg_b2 = (const float*)d_in[15];
    const float* sg_W1 = (const float*)d_in[16];
    const float* sg_b1 = (const float*)d_in[17];
    const float* sg_W2 = (const float*)d_in[18];
    const float* sg_b2 = (const float*)d_in[19];
    const float* sf_W1 = (const float*)d_in[20];
    const float* sf_b1 = (const float*)d_in[21];
    const float* sf_W2 = (const float*)d_in[22];
    const float* sf_b2 = (const float*)d_in[23];
    const float* oh_W1 = (const float*)d_in[24];
    const float* oh_b1 = (const float*)d_in[25];
    const float* oh_W2 = (const float*)d_in[26];
    const float* oh_b2 = (const float*)d_in[27];

    const int B = in_sizes[8];

    const int smem = SMEM_FLOATS * (int)sizeof(float);
    cudaFuncSetAttribute(cpm_fused_kernel, cudaFuncAttributeMaxDynamicSharedMemorySize, smem);

    const int grid = (B + BPB - 1) / BPB;
    cpm_fused_kernel<<<grid, 256, smem>>>(
        evidence, marker, src_idx, src_valid, tsym_idx, tsym_valid,
        tval_idx, tval_valid, query_idx, query_valid,
        symbol_emb, value_emb,
        mg_W1, mg_b1, mg_W2, mg_b2,
        sg_W1, sg_b1, sg_W2, sg_b2,
        sf_W1, sf_b1, sf_W2, sf_b2,
        oh_W1, oh_b1, oh_W2, oh_b2,
        (float*)d_out, B);
}